// round 5
// baseline (speedup 1.0000x reference)
#include <cuda_runtime.h>

#define NN 2048
#define DD 64
#define BM 128
#define BN 32
#define NKT (NN / BN)
#define ATT_SCALE 0.125f

#define KSTR 40            // % 32 == 8: conflict-free B-frag reads
#define VSTR 72            // % 32 == 8
#define QSTR 68            // % 32 == 4: conflict-free A-frag reads
#define OSTR 68
#define KBUF (DD * KSTR)   // 2560 floats
#define VBUF (BN * VSTR)   // 2304 floats
#define SMEM_FLOATS (2 * KBUF + 2 * VBUF)   // 9728 floats = 38.9 KB (Q stage + O reduce fit too)

__device__ __forceinline__ float f2tf32(float x) {
    unsigned y; asm("cvt.rna.tf32.f32 %0, %1;" : "=r"(y) : "f"(x));
    return __uint_as_float(y);
}
__device__ __forceinline__ float tanh_fast(float x) {
    float y; asm("tanh.approx.f32 %0, %1;" : "=f"(y) : "f"(x));
    return y;
}
__device__ __forceinline__ void mma8(float c[4], const float a[4], float b0, float b1) {
    asm volatile(
        "mma.sync.aligned.m16n8k8.row.col.f32.tf32.tf32.f32 "
        "{%0,%1,%2,%3}, {%4,%5,%6,%7}, {%8,%9}, {%0,%1,%2,%3};"
        : "+f"(c[0]), "+f"(c[1]), "+f"(c[2]), "+f"(c[3])
        : "r"(__float_as_uint(a[0])), "r"(__float_as_uint(a[1])),
          "r"(__float_as_uint(a[2])), "r"(__float_as_uint(a[3])),
          "r"(__float_as_uint(b0)),   "r"(__float_as_uint(b1)));
}

__global__ __launch_bounds__(256)
void selfatt_mma3_kernel(const float* __restrict__ Q, const float* __restrict__ K,
                         const float* __restrict__ V, const unsigned int* __restrict__ M,
                         float* __restrict__ O)
{
    __shared__ __align__(16) float smem[SMEM_FLOATS];

    const int tid  = threadIdx.x;
    const int lane = tid & 31;
    const int w    = tid >> 5;          // 0..7
    const int mg   = w >> 1;            // 0..3  m-group: 32 rows
    const int ng   = w & 1;             // 0..1  key-group: 16 keys
    const int lg   = lane >> 2;         // 0..7
    const int lt   = lane & 3;          // 0..3
    const int r0   = mg * 32;

    const int bh = blockIdx.y;
    const int q0 = blockIdx.x * BM;

    const float* qb = Q + (size_t)bh * NN * DD;
    const float* kb = K + (size_t)bh * NN * DD;
    const float* vb = V + (size_t)bh * NN * DD;
    const unsigned int* mb = M + (size_t)bh * NN * NN;

    // per-thread K/V tile load mappings (tile = 32 rows x 64 d)
    const int k_key = tid & 31;
    const int k_d0  = (tid >> 5) * 4;          // +0 / +32
    const int v_m0  = tid >> 4;                // +0 / +16
    const int v_d   = (tid & 15) * 4;

    // ---- stage Q (tf32), pull A-fragments to registers, free the SMEM ----
    for (int i = tid; i < BM * (DD / 4); i += 256) {
        int r = i >> 4, d4 = (i & 15) << 2;
        float4 t = *(const float4*)(qb + (size_t)(q0 + r) * DD + d4);
        float* dst = smem + r * QSTR + d4;
        dst[0] = f2tf32(t.x); dst[1] = f2tf32(t.y);
        dst[2] = f2tf32(t.z); dst[3] = f2tf32(t.w);
    }
    __syncthreads();

    float qa[8][2][4];   // [k8][mt][frag] : 32 rows x 64 k
    #pragma unroll
    for (int k8 = 0; k8 < 8; k8++)
        #pragma unroll
        for (int mt = 0; mt < 2; mt++) {
            const float* p0 = smem + (r0 + mt * 16 + lg) * QSTR + k8 * 8;
            const float* p8 = p0 + 8 * QSTR;
            qa[k8][mt][0] = p0[lt];     qa[k8][mt][1] = p8[lt];
            qa[k8][mt][2] = p0[lt + 4]; qa[k8][mt][3] = p8[lt + 4];
        }
    __syncthreads();

    // ---- tile 0 into buffer 0 ----
    {
        float* ks = smem;
        #pragma unroll
        for (int j = 0; j < 2; j++) {
            int d0 = k_d0 + j * 32;
            float4 t = *(const float4*)(kb + (size_t)k_key * DD + d0);
            ks[(d0 + 0) * KSTR + k_key] = f2tf32(t.x);
            ks[(d0 + 1) * KSTR + k_key] = f2tf32(t.y);
            ks[(d0 + 2) * KSTR + k_key] = f2tf32(t.z);
            ks[(d0 + 3) * KSTR + k_key] = f2tf32(t.w);
        }
        float* vs = smem + 2 * KBUF;
        #pragma unroll
        for (int j = 0; j < 2; j++) {
            int m = v_m0 + j * 16;
            float4 t = *(const float4*)(vb + (size_t)m * DD + v_d);
            float* d = vs + m * VSTR + v_d;
            d[0] = f2tf32(t.x); d[1] = f2tf32(t.y);
            d[2] = f2tf32(t.z); d[3] = f2tf32(t.w);
        }
    }

    // mask base: this warp's S block = rows r0..r0+31, keys ng*16..+15
    const unsigned int* mbase = mb + (size_t)(q0 + r0 + lg) * NN + ng * 16 + 2 * lt;
    uint2 mk[2][2][2];   // [mt][row8][nt]
    #pragma unroll
    for (int mt = 0; mt < 2; mt++)
        #pragma unroll
        for (int rr = 0; rr < 2; rr++)
            #pragma unroll
            for (int nt = 0; nt < 2; nt++)
                mk[mt][rr][nt] = *(const uint2*)(mbase + (size_t)(mt * 16 + rr * 8) * NN + nt * 8);

    __syncthreads();

    float oacc[2][8][4];   // [mt][nt][frag] : partial O (this warp's 16-key slice)
    #pragma unroll
    for (int mt = 0; mt < 2; mt++)
        #pragma unroll
        for (int nt = 0; nt < 8; nt++)
            #pragma unroll
            for (int i = 0; i < 4; i++) oacc[mt][nt][i] = 0.0f;

    int p = 0;
    for (int kt = 0; kt < NKT; kt++) {
        const int keyb = kt * BN;
        const bool pf = (kt + 1 < NKT);

        // prefetch next K/V tile + next mask tile
        float4 kf0, kf1, vf0, vf1;
        uint2 mkn[2][2][2];
        if (pf) {
            const int nb = keyb + BN;
            kf0 = *(const float4*)(kb + (size_t)(nb + k_key) * DD + k_d0);
            kf1 = *(const float4*)(kb + (size_t)(nb + k_key) * DD + k_d0 + 32);
            vf0 = *(const float4*)(vb + (size_t)(nb + v_m0) * DD + v_d);
            vf1 = *(const float4*)(vb + (size_t)(nb + v_m0 + 16) * DD + v_d);
            #pragma unroll
            for (int mt = 0; mt < 2; mt++)
                #pragma unroll
                for (int rr = 0; rr < 2; rr++)
                    #pragma unroll
                    for (int nt = 0; nt < 2; nt++)
                        mkn[mt][rr][nt] = *(const uint2*)(mbase + nb +
                                            (size_t)(mt * 16 + rr * 8) * NN + nt * 8);
        }

        // ---- GEMM1: S[32 x 16] per warp ----
        const float* Kp = smem + p * KBUF;
        float sc[2][2][4];
        #pragma unroll
        for (int mt = 0; mt < 2; mt++)
            #pragma unroll
            for (int nt = 0; nt < 2; nt++)
                #pragma unroll
                for (int i = 0; i < 4; i++) sc[mt][nt][i] = 0.0f;

        #pragma unroll
        for (int k8 = 0; k8 < 8; k8++) {
            const float* kr0 = Kp + (k8 * 8 + lt) * KSTR + ng * 16 + lg;
            const float* kr1 = kr0 + 4 * KSTR;
            #pragma unroll
            for (int nt = 0; nt < 2; nt++) {
                float b0 = kr0[nt * 8], b1 = kr1[nt * 8];
                mma8(sc[0][nt], qa[k8][0], b0, b1);
                mma8(sc[1][nt], qa[k8][1], b0, b1);
            }
        }

        // ---- mask + tanh + C->A shuffle transpose + GEMM2 ----
        const float* Vp = smem + 2 * KBUF + p * VBUF;
        #pragma unroll
        for (int mt = 0; mt < 2; mt++) {
            #pragma unroll
            for (int kb8 = 0; kb8 < 2; kb8++) {
                float w0 = mk[mt][0][kb8].x ? 0.0f : tanh_fast(sc[mt][kb8][0] * ATT_SCALE);
                float w1 = mk[mt][0][kb8].y ? 0.0f : tanh_fast(sc[mt][kb8][1] * ATT_SCALE);
                float w2 = mk[mt][1][kb8].x ? 0.0f : tanh_fast(sc[mt][kb8][2] * ATT_SCALE);
                float w3 = mk[mt][1][kb8].y ? 0.0f : tanh_fast(sc[mt][kb8][3] * ATT_SCALE);

                const int s0 = (lane & 28) | (lt >> 1);
                const int s1 = s0 + 2;
                float t0, t1, aS[4];
                t0 = __shfl_sync(0xffffffffu, w0, s0);
                t1 = __shfl_sync(0xffffffffu, w1, s0);
                aS[0] = (lt & 1) ? t1 : t0;
                t0 = __shfl_sync(0xffffffffu, w0, s1);
                t1 = __shfl_sync(0xffffffffu, w1, s1);
                aS[2] = (lt & 1) ? t1 : t0;
                t0 = __shfl_sync(0xffffffffu, w2, s0);
                t1 = __shfl_sync(0xffffffffu, w3, s0);
                aS[1] = (lt & 1) ? t1 : t0;
                t0 = __shfl_sync(0xffffffffu, w2, s1);
                t1 = __shfl_sync(0xffffffffu, w3, s1);
                aS[3] = (lt & 1) ? t1 : t0;
                aS[0] = f2tf32(aS[0]); aS[1] = f2tf32(aS[1]);
                aS[2] = f2tf32(aS[2]); aS[3] = f2tf32(aS[3]);

                const float* vr0 = Vp + (ng * 16 + kb8 * 8 + lt) * VSTR + lg;
                const float* vr1 = vr0 + 4 * VSTR;
                #pragma unroll
                for (int nt = 0; nt < 8; nt++)
                    mma8(oacc[mt][nt], aS, vr0[nt * 8], vr1[nt * 8]);
            }
        }

        // ---- commit prefetched tile, rotate mask regs ----
        if (pf) {
            float* kn = smem + (p ^ 1) * KBUF;
            kn[(k_d0 + 0) * KSTR + k_key] = f2tf32(kf0.x);
            kn[(k_d0 + 1) * KSTR + k_key] = f2tf32(kf0.y);
            kn[(k_d0 + 2) * KSTR + k_key] = f2tf32(kf0.z);
            kn[(k_d0 + 3) * KSTR + k_key] = f2tf32(kf0.w);
            kn[(k_d0 + 32) * KSTR + k_key] = f2tf32(kf1.x);
            kn[(k_d0 + 33) * KSTR + k_key] = f2tf32(kf1.y);
            kn[(k_d0 + 34) * KSTR + k_key] = f2tf32(kf1.z);
            kn[(k_d0 + 35) * KSTR + k_key] = f2tf32(kf1.w);
            float* vn = smem + 2 * KBUF + (p ^ 1) * VBUF;
            float* d0p = vn + v_m0 * VSTR + v_d;
            d0p[0] = f2tf32(vf0.x); d0p[1] = f2tf32(vf0.y);
            d0p[2] = f2tf32(vf0.z); d0p[3] = f2tf32(vf0.w);
            float* d1p = vn + (v_m0 + 16) * VSTR + v_d;
            d1p[0] = f2tf32(vf1.x); d1p[1] = f2tf32(vf1.y);
            d1p[2] = f2tf32(vf1.z); d1p[3] = f2tf32(vf1.w);
            #pragma unroll
            for (int mt = 0; mt < 2; mt++)
                #pragma unroll
                for (int rr = 0; rr < 2; rr++)
                    #pragma unroll
                    for (int nt = 0; nt < 2; nt++)
                        mk[mt][rr][nt] = mkn[mt][rr][nt];
        }
        __syncthreads();
        p ^= 1;
    }

    // ---- reduce partial O across the key-group pair, write out ----
    float* Os = smem;   // 128 x OSTR, K/V buffers dead
    if (ng == 1) {
        #pragma unroll
        for (int mt = 0; mt < 2; mt++)
            #pragma unroll
            for (int nt = 0; nt < 8; nt++) {
                const int r = r0 + mt * 16 + lg;
                const int c = nt * 8 + 2 * lt;
                Os[r * OSTR + c]           = oacc[mt][nt][0];
                Os[r * OSTR + c + 1]       = oacc[mt][nt][1];
                Os[(r + 8) * OSTR + c]     = oacc[mt][nt][2];
                Os[(r + 8) * OSTR + c + 1] = oacc[mt][nt][3];
            }
    }
    __syncthreads();
    if (ng == 0) {
        #pragma unroll
        for (int mt = 0; mt < 2; mt++)
            #pragma unroll
            for (int nt = 0; nt < 8; nt++) {
                const int r = r0 + mt * 16 + lg;
                const int c = nt * 8 + 2 * lt;
                float o0 = oacc[mt][nt][0] + Os[r * OSTR + c];
                float o1 = oacc[mt][nt][1] + Os[r * OSTR + c + 1];
                float o2 = oacc[mt][nt][2] + Os[(r + 8) * OSTR + c];
                float o3 = oacc[mt][nt][3] + Os[(r + 8) * OSTR + c + 1];
                float* op = O + ((size_t)bh * NN + q0 + r) * DD + c;
                *(float2*)op            = make_float2(o0, o1);
                *(float2*)(op + 8 * DD) = make_float2(o2, o3);
            }
    }
}

extern "C" void kernel_launch(void* const* d_in, const int* in_sizes, int n_in,
                              void* d_out, int out_size)
{
    const float* q = (const float*)d_in[0];
    const float* k = (const float*)d_in[1];
    const float* v = (const float*)d_in[2];
    const unsigned int* m = (const unsigned int*)d_in[3];
    float* o = (float*)d_out;

    dim3 grid(NN / BM, 32);   // 16 x 32 = 512 CTAs
    selfatt_mma3_kernel<<<grid, 256>>>(q, k, v, m, o);
}

// round 6
// speedup vs baseline: 1.3550x; 1.3550x over previous
#include <cuda_runtime.h>
#include <cuda_fp16.h>

#define NN 2048
#define DD 64
#define BM 128
#define BN 32
#define NKT (NN / BN)
#define ATT_SCALE 0.125f

// 32-bit-word strides (data + pad, all conflict-free for their access patterns)
#define QSTR2 36               // Q stage: words per row (32 data + 4 pad)
#define KSTR2 36               // K tile:  words per key row (d-contiguous halves)
#define VSTR2 20               // V tile:  words per d row (16 data m-contig + 4 pad)
#define KBUFW (BN * KSTR2)     // 1152 words
#define VBUFW (DD * VSTR2)     // 1280 words
#define SMEM_WORDS (2 * KBUFW + 2 * VBUFW)   // 4864 words = 19456 B (Q stage 4608 fits)

__device__ __forceinline__ float tanh_fast(float x) {
    float y; asm("tanh.approx.f32 %0, %1;" : "=f"(y) : "f"(x));
    return y;
}
__device__ __forceinline__ unsigned h2(float lo, float hi) {
    __half2 t = __floats2half2_rn(lo, hi);     // lo -> .x (low half = smaller k index)
    return *reinterpret_cast<unsigned*>(&t);
}
__device__ __forceinline__ void mma16(float c[4], const unsigned a[4],
                                      unsigned b0, unsigned b1) {
    asm volatile(
        "mma.sync.aligned.m16n8k16.row.col.f32.f16.f16.f32 "
        "{%0,%1,%2,%3}, {%4,%5,%6,%7}, {%8,%9}, {%0,%1,%2,%3};"
        : "+f"(c[0]), "+f"(c[1]), "+f"(c[2]), "+f"(c[3])
        : "r"(a[0]), "r"(a[1]), "r"(a[2]), "r"(a[3]), "r"(b0), "r"(b1));
}

__global__ __launch_bounds__(256, 2)
void selfatt_h16_kernel(const float* __restrict__ Q, const float* __restrict__ K,
                        const float* __restrict__ V, const unsigned int* __restrict__ M,
                        float* __restrict__ O)
{
    __shared__ __align__(16) unsigned smem[SMEM_WORDS];

    const int tid  = threadIdx.x;
    const int lane = tid & 31;
    const int w    = tid >> 5;      // 0..7
    const int lg   = lane >> 2;     // 0..7
    const int lt   = lane & 3;      // 0..3
    const int r0   = w * 16;        // warp's 16 S-rows

    const int bh = blockIdx.y;
    const int q0 = blockIdx.x * BM;

    const float* qb = Q + (size_t)bh * NN * DD;
    const float* kb = K + (size_t)bh * NN * DD;
    const float* vb = V + (size_t)bh * NN * DD;
    const unsigned int* mb = M + (size_t)bh * NN * NN;

    // staging maps: K rows (and Q passes): row = tid>>3, d-group of 8 = tid&7
    const int s_row = tid >> 3;     // 0..31
    const int s_dg  = tid & 7;      // 0..7
    // V staging: warp w owns d rows 8w..8w+7, lane = m
    const int v_d0  = w * 8;

    // ---- stage Q as fp16 (half2 words), then pull A-fragments to registers ----
    #pragma unroll
    for (int pass = 0; pass < 4; pass++) {
        int r = pass * 32 + s_row;
        const float4* src = (const float4*)(qb + (size_t)(q0 + r) * DD + s_dg * 8);
        float4 t0 = src[0], t1 = src[1];
        uint4 u;
        u.x = h2(t0.x, t0.y); u.y = h2(t0.z, t0.w);
        u.z = h2(t1.x, t1.y); u.w = h2(t1.z, t1.w);
        *(uint4*)(smem + r * QSTR2 + s_dg * 4) = u;
    }
    __syncthreads();

    unsigned qa[4][4];   // [kb16][frag]
    #pragma unroll
    for (int kb16 = 0; kb16 < 4; kb16++) {
        const unsigned* p0 = smem + (r0 + lg) * QSTR2 + kb16 * 8;
        const unsigned* p8 = p0 + 8 * QSTR2;
        qa[kb16][0] = p0[lt];     qa[kb16][1] = p8[lt];
        qa[kb16][2] = p0[lt + 4]; qa[kb16][3] = p8[lt + 4];
    }
    __syncthreads();    // Q staging dead -> K/V double buffers

    // ---- stage tile 0 into buffer 0 ----
    {
        const float4* ks = (const float4*)(kb + (size_t)s_row * DD + s_dg * 8);
        float4 t0 = ks[0], t1 = ks[1];
        uint4 u;
        u.x = h2(t0.x, t0.y); u.y = h2(t0.z, t0.w);
        u.z = h2(t1.x, t1.y); u.w = h2(t1.z, t1.w);
        *(uint4*)(smem + s_row * KSTR2 + s_dg * 4) = u;

        const float4* vs = (const float4*)(vb + (size_t)lane * DD + v_d0);
        float4 a = vs[0], b = vs[1];
        float f[8] = {a.x, a.y, a.z, a.w, b.x, b.y, b.z, b.w};
        float p_[8];
        #pragma unroll
        for (int j = 0; j < 8; j++) p_[j] = __shfl_xor_sync(0xffffffffu, f[j], 1);
        unsigned* vbuf = smem + 2 * KBUFW;
        if ((lane & 1) == 0) {
            #pragma unroll
            for (int j = 0; j < 4; j++)
                vbuf[(v_d0 + j) * VSTR2 + (lane >> 1)] = h2(f[j], p_[j]);
        } else {
            #pragma unroll
            for (int j = 4; j < 8; j++)
                vbuf[(v_d0 + j) * VSTR2 + (lane >> 1)] = h2(p_[j], f[j]);
        }
    }
    __syncthreads();

    float oacc[8][4];
    #pragma unroll
    for (int nt = 0; nt < 8; nt++)
        #pragma unroll
        for (int i = 0; i < 4; i++) oacc[nt][i] = 0.0f;

    const unsigned int* mrow0 = mb + (size_t)(q0 + r0 + lg) * NN + 2 * lt;
    const unsigned int* mrow8 = mrow0 + 8 * (size_t)NN;

    int p = 0;
    for (int kt = 0; kt < NKT; kt++) {
        const int keyb = kt * BN;
        const bool pf = (kt + 1 < NKT);

        // mask for THIS tile (issued first; lands during GEMM1)
        uint2 mk0[4], mk8[4];
        #pragma unroll
        for (int nt = 0; nt < 4; nt++) {
            mk0[nt] = *(const uint2*)(mrow0 + keyb + nt * 8);
            mk8[nt] = *(const uint2*)(mrow8 + keyb + nt * 8);
        }
        // prefetch NEXT K/V tile into registers
        float4 kf0, kf1, vf0, vf1;
        if (pf) {
            const int nb = keyb + BN;
            const float4* ks = (const float4*)(kb + (size_t)(nb + s_row) * DD + s_dg * 8);
            kf0 = ks[0]; kf1 = ks[1];
            const float4* vs = (const float4*)(vb + (size_t)(nb + lane) * DD + v_d0);
            vf0 = vs[0]; vf1 = vs[1];
        }

        // ---- GEMM1: S[16x32] per warp, 16 HMMAs ----
        const unsigned* Kp = smem + p * KBUFW;
        float sc[4][4];
        #pragma unroll
        for (int nt = 0; nt < 4; nt++)
            #pragma unroll
            for (int i = 0; i < 4; i++) sc[nt][i] = 0.0f;

        #pragma unroll
        for (int kb16 = 0; kb16 < 4; kb16++) {
            #pragma unroll
            for (int nt = 0; nt < 4; nt++) {
                const unsigned* kr = Kp + (nt * 8 + lg) * KSTR2 + kb16 * 8;
                mma16(sc[nt], qa[kb16], kr[lt], kr[lt + 4]);
            }
        }

        // ---- mask + tanh + direct C->A reuse + GEMM2 (16 HMMAs) ----
        const unsigned* Vp = smem + 2 * KBUFW + p * VBUFW;
        #pragma unroll
        for (int kb2 = 0; kb2 < 2; kb2++) {
            unsigned aS[4];
            {
                const int nt = 2 * kb2;
                float w0 = mk0[nt].x ? 0.0f : tanh_fast(sc[nt][0] * ATT_SCALE);
                float w1 = mk0[nt].y ? 0.0f : tanh_fast(sc[nt][1] * ATT_SCALE);
                float w2 = mk8[nt].x ? 0.0f : tanh_fast(sc[nt][2] * ATT_SCALE);
                float w3 = mk8[nt].y ? 0.0f : tanh_fast(sc[nt][3] * ATT_SCALE);
                aS[0] = h2(w0, w1);   // (row lg,   k=2lt,2lt+1)
                aS[1] = h2(w2, w3);   // (row lg+8, k=2lt,2lt+1)
            }
            {
                const int nt = 2 * kb2 + 1;
                float w0 = mk0[nt].x ? 0.0f : tanh_fast(sc[nt][0] * ATT_SCALE);
                float w1 = mk0[nt].y ? 0.0f : tanh_fast(sc[nt][1] * ATT_SCALE);
                float w2 = mk8[nt].x ? 0.0f : tanh_fast(sc[nt][2] * ATT_SCALE);
                float w3 = mk8[nt].y ? 0.0f : tanh_fast(sc[nt][3] * ATT_SCALE);
                aS[2] = h2(w0, w1);   // (row lg,   k=2lt+8,2lt+9)
                aS[3] = h2(w2, w3);   // (row lg+8, k=2lt+8,2lt+9)
            }
            #pragma unroll
            for (int nt = 0; nt < 8; nt++) {
                const unsigned* vr = Vp + (nt * 8 + lg) * VSTR2 + kb2 * 8;
                mma16(oacc[nt], aS, vr[lt], vr[lt + 4]);
            }
        }

        // ---- commit prefetched tile into other buffer ----
        if (pf) {
            uint4 u;
            u.x = h2(kf0.x, kf0.y); u.y = h2(kf0.z, kf0.w);
            u.z = h2(kf1.x, kf1.y); u.w = h2(kf1.z, kf1.w);
            *(uint4*)(smem + (p ^ 1) * KBUFW + s_row * KSTR2 + s_dg * 4) = u;

            float f[8] = {vf0.x, vf0.y, vf0.z, vf0.w, vf1.x, vf1.y, vf1.z, vf1.w};
            float p_[8];
            #pragma unroll
            for (int j = 0; j < 8; j++) p_[j] = __shfl_xor_sync(0xffffffffu, f[j], 1);
            unsigned* vn = smem + 2 * KBUFW + (p ^ 1) * VBUFW;
            if ((lane & 1) == 0) {
                #pragma unroll
                for (int j = 0; j < 4; j++)
                    vn[(v_d0 + j) * VSTR2 + (lane >> 1)] = h2(f[j], p_[j]);
            } else {
                #pragma unroll
                for (int j = 4; j < 8; j++)
                    vn[(v_d0 + j) * VSTR2 + (lane >> 1)] = h2(p_[j], f[j]);
            }
        }
        __syncthreads();
        p ^= 1;
    }

    // ---- epilogue ----
    #pragma unroll
    for (int nt = 0; nt < 8; nt++) {
        float* o0 = O + ((size_t)bh * NN + q0 + r0 + lg) * DD + nt * 8 + 2 * lt;
        *(float2*)o0            = make_float2(oacc[nt][0], oacc[nt][1]);
        *(float2*)(o0 + 8 * DD) = make_float2(oacc[nt][2], oacc[nt][3]);
    }
}

extern "C" void kernel_launch(void* const* d_in, const int* in_sizes, int n_in,
                              void* d_out, int out_size)
{
    const float* q = (const float*)d_in[0];
    const float* k = (const float*)d_in[1];
    const float* v = (const float*)d_in[2];
    const unsigned int* m = (const unsigned int*)d_in[3];
    float* o = (float*)d_out;

    dim3 grid(NN / BM, 32);   // 16 x 32 = 512 CTAs
    selfatt_h16_kernel<<<grid, 256>>>(q, k, v, m, o);
}

// round 8
// speedup vs baseline: 1.3889x; 1.0250x over previous
#include <cuda_runtime.h>
#include <cuda_fp16.h>

#define NN 2048
#define DD 64
#define BM 128
#define BN 32
#define NKT (NN / BN)
#define ATT_SCALE 0.125f

#define QSTR2 36               // Q stage words/row
#define KSTR2 36               // K tile words/key-row
#define VSTR2 20               // V tile words/d-row
#define KBUFW (BN * KSTR2)     // 1152 words
#define VBUFW (DD * VSTR2)     // 1280 words
#define SMEM_WORDS (2 * KBUFW + 2 * VBUFW)   // 4864 words = 19456 B

__device__ __forceinline__ float tanh_fast(float x) {
    float y; asm("tanh.approx.f32 %0, %1;" : "=f"(y) : "f"(x));
    return y;
}
__device__ __forceinline__ unsigned h2(float lo, float hi) {
    __half2 t = __floats2half2_rn(lo, hi);
    return *reinterpret_cast<unsigned*>(&t);
}
__device__ __forceinline__ void mma16(float c[4], const unsigned a[4],
                                      unsigned b0, unsigned b1) {
    asm volatile(
        "mma.sync.aligned.m16n8k16.row.col.f32.f16.f16.f32 "
        "{%0,%1,%2,%3}, {%4,%5,%6,%7}, {%8,%9}, {%0,%1,%2,%3};"
        : "+f"(c[0]), "+f"(c[1]), "+f"(c[2]), "+f"(c[3])
        : "r"(a[0]), "r"(a[1]), "r"(a[2]), "r"(a[3]), "r"(b0), "r"(b1));
}

__global__ __launch_bounds__(256, 2)
void selfatt_h16p_kernel(const float* __restrict__ Q, const float* __restrict__ K,
                         const float* __restrict__ V, const unsigned int* __restrict__ M,
                         float* __restrict__ O)
{
    __shared__ __align__(16) unsigned smem[SMEM_WORDS];

    const int tid  = threadIdx.x;
    const int lane = tid & 31;
    const int w    = tid >> 5;
    const int lg   = lane >> 2;
    const int lt   = lane & 3;
    const int r0   = w * 16;

    const int bh = blockIdx.y;
    const int q0 = blockIdx.x * BM;

    const float* qb = Q + (size_t)bh * NN * DD;
    const float* kb = K + (size_t)bh * NN * DD;
    const float* vb = V + (size_t)bh * NN * DD;
    const unsigned int* mb = M + (size_t)bh * NN * NN;

    const int s_row = tid >> 3;     // K staging: key row 0..31
    const int s_dg  = tid & 7;      // K staging: d-group of 8
    const int v_d0  = w * 8;        // V staging: d base

    // ---- stage Q fp16, pull A-fragments ----
    #pragma unroll
    for (int pass = 0; pass < 4; pass++) {
        int r = pass * 32 + s_row;
        const float4* src = (const float4*)(qb + (size_t)(q0 + r) * DD + s_dg * 8);
        float4 t0 = src[0], t1 = src[1];
        *(uint4*)(smem + r * QSTR2 + s_dg * 4) =
            make_uint4(h2(t0.x, t0.y), h2(t0.z, t0.w), h2(t1.x, t1.y), h2(t1.z, t1.w));
    }
    __syncthreads();
    unsigned qa[4][4];
    #pragma unroll
    for (int kb16 = 0; kb16 < 4; kb16++) {
        const unsigned* p0 = smem + (r0 + lg) * QSTR2 + kb16 * 8;
        const unsigned* p8 = p0 + 8 * QSTR2;
        qa[kb16][0] = p0[lt];     qa[kb16][1] = p8[lt];
        qa[kb16][2] = p0[lt + 4]; qa[kb16][3] = p8[lt + 4];
    }
    __syncthreads();

    // ---- stage K(0)->buf0, K(1)->buf1, V(0)->Vbuf0 ----
    {
        #pragma unroll
        for (int t = 0; t < 2; t++) {
            const float4* ks = (const float4*)(kb + (size_t)(t * BN + s_row) * DD + s_dg * 8);
            float4 t0 = ks[0], t1 = ks[1];
            *(uint4*)(smem + t * KBUFW + s_row * KSTR2 + s_dg * 4) =
                make_uint4(h2(t0.x, t0.y), h2(t0.z, t0.w), h2(t1.x, t1.y), h2(t1.z, t1.w));
        }
        const float4* vs = (const float4*)(vb + (size_t)lane * DD + v_d0);
        float4 a = vs[0], b = vs[1];
        float f[8] = {a.x, a.y, a.z, a.w, b.x, b.y, b.z, b.w};
        float g[8];
        #pragma unroll
        for (int j = 0; j < 8; j++) g[j] = __shfl_xor_sync(0xffffffffu, f[j], 1);
        unsigned* vbuf = smem + 2 * KBUFW;
        if (!(lane & 1)) {
            #pragma unroll
            for (int j = 0; j < 4; j++)
                vbuf[(v_d0 + j) * VSTR2 + (lane >> 1)] = h2(f[j], g[j]);
        } else {
            #pragma unroll
            for (int j = 4; j < 8; j++)
                vbuf[(v_d0 + j) * VSTR2 + (lane >> 1)] = h2(g[j], f[j]);
        }
    }

    const unsigned int* mrow0 = mb + (size_t)(q0 + r0 + lg) * NN + 2 * lt;
    const unsigned int* mrow8 = mrow0 + 8 * (size_t)NN;
    uint2 mk0[4], mk8[4];
    #pragma unroll
    for (int nt = 0; nt < 4; nt++) {
        mk0[nt] = *(const uint2*)(mrow0 + nt * 8);
        mk8[nt] = *(const uint2*)(mrow8 + nt * 8);
    }
    __syncthreads();

    float oacc[8][4];
    #pragma unroll
    for (int nt = 0; nt < 8; nt++)
        #pragma unroll
        for (int i = 0; i < 4; i++) oacc[nt][i] = 0.0f;

    // ---- pre-loop GEMM1(0) from Kbuf0 ----
    float sc[4][4];
    #pragma unroll
    for (int nt = 0; nt < 4; nt++)
        #pragma unroll
        for (int i = 0; i < 4; i++) sc[nt][i] = 0.0f;
    #pragma unroll
    for (int kb16 = 0; kb16 < 4; kb16++)
        #pragma unroll
        for (int nt = 0; nt < 4; nt++) {
            const unsigned* kr = smem + (nt * 8 + lg) * KSTR2 + kb16 * 8;
            mma16(sc[nt], qa[kb16], kr[lt], kr[lt + 4]);
        }
    __syncthreads();   // isolate GEMM1(0) reads from body-0 K stores

    for (int it = 0; it < NKT; it++) {
        const bool hasN1 = (it + 1 < NKT);
        const bool hasN2 = (it + 2 < NKT);

        // ---- LDG prefetch: K(it+2), V(it+1), mask(it+1) ----
        float4 kf0, kf1, vf0, vf1;
        uint2 mn0[4], mn8[4];
        if (hasN2) {
            const float4* ks = (const float4*)(kb + (size_t)((it + 2) * BN + s_row) * DD + s_dg * 8);
            kf0 = ks[0]; kf1 = ks[1];
        }
        if (hasN1) {
            const float4* vs = (const float4*)(vb + (size_t)((it + 1) * BN + lane) * DD + v_d0);
            vf0 = vs[0]; vf1 = vs[1];
            const int nb = (it + 1) * BN;
            #pragma unroll
            for (int nt = 0; nt < 4; nt++) {
                mn0[nt] = *(const uint2*)(mrow0 + nb + nt * 8);
                mn8[nt] = *(const uint2*)(mrow8 + nb + nt * 8);
            }
        }

        // ---- tanh + mask + pack S(it) (consumes sc) ----
        unsigned aS[2][4];
        #pragma unroll
        for (int kb2 = 0; kb2 < 2; kb2++) {
            {
                const int nt = 2 * kb2;
                float w0 = mk0[nt].x ? 0.0f : tanh_fast(sc[nt][0] * ATT_SCALE);
                float w1 = mk0[nt].y ? 0.0f : tanh_fast(sc[nt][1] * ATT_SCALE);
                float w2 = mk8[nt].x ? 0.0f : tanh_fast(sc[nt][2] * ATT_SCALE);
                float w3 = mk8[nt].y ? 0.0f : tanh_fast(sc[nt][3] * ATT_SCALE);
                aS[kb2][0] = h2(w0, w1);
                aS[kb2][1] = h2(w2, w3);
            }
            {
                const int nt = 2 * kb2 + 1;
                float w0 = mk0[nt].x ? 0.0f : tanh_fast(sc[nt][0] * ATT_SCALE);
                float w1 = mk0[nt].y ? 0.0f : tanh_fast(sc[nt][1] * ATT_SCALE);
                float w2 = mk8[nt].x ? 0.0f : tanh_fast(sc[nt][2] * ATT_SCALE);
                float w3 = mk8[nt].y ? 0.0f : tanh_fast(sc[nt][3] * ATT_SCALE);
                aS[kb2][2] = h2(w0, w1);
                aS[kb2][3] = h2(w2, w3);
            }
        }

        // ---- GEMM1(it+1): refill sc from Kbuf (it+1)&1 (independent of GEMM2) ----
        if (hasN1) {
            #pragma unroll
            for (int nt = 0; nt < 4; nt++)
                #pragma unroll
                for (int i = 0; i < 4; i++) sc[nt][i] = 0.0f;
            const unsigned* Kp = smem + ((it + 1) & 1) * KBUFW;
            #pragma unroll
            for (int kb16 = 0; kb16 < 4; kb16++)
                #pragma unroll
                for (int nt = 0; nt < 4; nt++) {
                    const unsigned* kr = Kp + (nt * 8 + lg) * KSTR2 + kb16 * 8;
                    mma16(sc[nt], qa[kb16], kr[lt], kr[lt + 4]);
                }
        }

        // ---- GEMM2(it): oacc += S . V^T from Vbuf it&1 ----
        {
            const unsigned* Vp = smem + 2 * KBUFW + (it & 1) * VBUFW;
            #pragma unroll
            for (int kb2 = 0; kb2 < 2; kb2++)
                #pragma unroll
                for (int nt = 0; nt < 8; nt++) {
                    const unsigned* vr = Vp + (nt * 8 + lg) * VSTR2 + kb2 * 8;
                    mma16(oacc[nt], aS[kb2], vr[lt], vr[lt + 4]);
                }
        }

        // ---- STS commits: K(it+2)->Kbuf it&1, V(it+1)->Vbuf (it+1)&1 ----
        if (hasN2) {
            *(uint4*)(smem + (it & 1) * KBUFW + s_row * KSTR2 + s_dg * 4) =
                make_uint4(h2(kf0.x, kf0.y), h2(kf0.z, kf0.w),
                           h2(kf1.x, kf1.y), h2(kf1.z, kf1.w));
        }
        if (hasN1) {
            float f[8] = {vf0.x, vf0.y, vf0.z, vf0.w, vf1.x, vf1.y, vf1.z, vf1.w};
            float g[8];
            #pragma unroll
            for (int j = 0; j < 8; j++) g[j] = __shfl_xor_sync(0xffffffffu, f[j], 1);
            unsigned* vn = smem + 2 * KBUFW + ((it + 1) & 1) * VBUFW;
            if (!(lane & 1)) {
                #pragma unroll
                for (int j = 0; j < 4; j++)
                    vn[(v_d0 + j) * VSTR2 + (lane >> 1)] = h2(f[j], g[j]);
            } else {
                #pragma unroll
                for (int j = 4; j < 8; j++)
                    vn[(v_d0 + j) * VSTR2 + (lane >> 1)] = h2(g[j], f[j]);
            }
            #pragma unroll
            for (int nt = 0; nt < 4; nt++) { mk0[nt] = mn0[nt]; mk8[nt] = mn8[nt]; }
        }
        __syncthreads();
    }

    // ---- epilogue ----
    #pragma unroll
    for (int nt = 0; nt < 8; nt++) {
        float* o0 = O + ((size_t)bh * NN + q0 + r0 + lg) * DD + nt * 8 + 2 * lt;
        *(float2*)o0            = make_float2(oacc[nt][0], oacc[nt][1]);
        *(float2*)(o0 + 8 * DD) = make_float2(oacc[nt][2], oacc[nt][3]);
    }
}

extern "C" void kernel_launch(void* const* d_in, const int* in_sizes, int n_in,
                              void* d_out, int out_size)
{
    const float* q = (const float*)d_in[0];
    const float* k = (const float*)d_in[1];
    const float* v = (const float*)d_in[2];
    const unsigned int* m = (const unsigned int*)d_in[3];
    float* o = (float*)d_out;

    dim3 grid(NN / BM, 32);   // 16 x 32 = 512 CTAs
    selfatt_h16p_kernel<<<grid, 256>>>(q, k, v, m, o);
}